// round 9
// baseline (speedup 1.0000x reference)
#include <cuda_runtime.h>
#include <cuda_fp16.h>

#define VOCAB   50257
#define DIM     128
#define BATCH   32
#define M_SLOTS 512
#define S_TOK   6
#define T_TREE  128
#define L_TOK   64
#define SLOTS   (M_SLOTS + T_TREE)      // 640
#define BLK_PER_TB   (SLOTS / 8)        // 80 blocks per (table, batch)
#define GBLK_PER_TAB (BATCH * BLK_PER_TB) // 2560
#define CN  ((size_t)3 * VOCAB * DIM)   // floats in tables 1..3

// fp16 copy of tables 1..3 (38.6 MB), fp16 slot memories (15.7 MB)
__device__ __align__(16) __half g_Ch[CN];
__device__ __align__(16) __half g_Mh[(size_t)3 * BATCH * SLOTS * DIM];
__device__ __align__(16) float  g_u2[BATCH * DIM];
__device__ int g_cnt[2 * BATCH];   // [b]: M1+M2 arrivals; [BATCH+b]: M3+hop1

__device__ __forceinline__ float warp_max(float v) {
    #pragma unroll
    for (int o = 16; o; o >>= 1) v = fmaxf(v, __shfl_xor_sync(0xffffffffu, v, o));
    return v;
}
__device__ __forceinline__ float warp_sum(float v) {
    #pragma unroll
    for (int o = 16; o; o >>= 1) v += __shfl_xor_sync(0xffffffffu, v, o);
    return v;
}
__device__ __forceinline__ void acc_u2(float4& a, uint2 v) {
    float2 f0 = __half22float2(*reinterpret_cast<__half2*>(&v.x));
    float2 f1 = __half22float2(*reinterpret_cast<__half2*>(&v.y));
    a.x += f0.x; a.y += f0.y; a.z += f1.x; a.w += f1.y;
}

struct HopShared {
    float  score[SLOTS];    // 2560 B
    float4 part[8][32];     // 4096 B
    float  u[DIM];          // 512 B
    float  red[8];
};

// ---------------------------------------------------------------------------
// K1: convert C tables 1..3 to fp16. Streaming reads (evict-first) so the
// freshly written fp16 table stays L2-resident for the gather.
// ---------------------------------------------------------------------------
__global__ void __launch_bounds__(256) convert_kernel(const float* __restrict__ C)
{
    const size_t i = ((size_t)blockIdx.x * 256 + threadIdx.x) * 8;
    if (i >= CN) return;
    const float4* src = reinterpret_cast<const float4*>(C + (size_t)VOCAB * DIM + i);
    float4 a = __ldcs(src);
    float4 b = __ldcs(src + 1);
    union { __half2 h[4]; uint4 u; } cv;
    cv.h[0] = __floats2half2_rn(a.x, a.y);
    cv.h[1] = __floats2half2_rn(a.z, a.w);
    cv.h[2] = __floats2half2_rn(b.x, b.y);
    cv.h[3] = __floats2half2_rn(b.z, b.w);
    *reinterpret_cast<uint4*>(g_Ch + i) = cv.u;
}

// ---------------------------------------------------------------------------
// One full hop for batch b inside ONE block: exact softmax over 640 slots.
// sh.u must hold the input state u; writes dst[0..127] (warp 0).
// ---------------------------------------------------------------------------
__device__ void hop_block(HopShared& sh, const __half* __restrict__ Mk,
                          const __half* __restrict__ Mv, float* __restrict__ dst)
{
    const int tid  = threadIdx.x;
    const int w    = tid >> 5;
    const int lane = tid & 31;

    const float4 u4 = reinterpret_cast<const float4*>(sh.u)[lane];

    // scores: warp w handles slots w + 8k
    #pragma unroll 8
    for (int k = 0; k < BLK_PER_TB; ++k) {
        const int slot = w + 8 * k;
        uint2 raw = reinterpret_cast<const uint2*>(Mk + (size_t)slot * DIM)[lane];
        float4 v = make_float4(0.f, 0.f, 0.f, 0.f);
        acc_u2(v, raw);
        float p = v.x * u4.x + v.y * u4.y + v.z * u4.z + v.w * u4.w;
        p = warp_sum(p);
        if (lane == 0) sh.score[slot] = p;
    }
    __syncthreads();

    // block softmax over 640
    float mx = -1e30f;
    for (int i = tid; i < SLOTS; i += 256) mx = fmaxf(mx, sh.score[i]);
    mx = warp_max(mx);
    if (lane == 0) sh.red[w] = mx;
    __syncthreads();
    mx = sh.red[0];
    #pragma unroll
    for (int i = 1; i < 8; ++i) mx = fmaxf(mx, sh.red[i]);

    float ss = 0.f;
    for (int i = tid; i < SLOTS; i += 256) {
        float e = __expf(sh.score[i] - mx);
        sh.score[i] = e;
        ss += e;
    }
    ss = warp_sum(ss);
    __syncthreads();                  // red (maxes) fully consumed
    if (lane == 0) sh.red[w] = ss;
    __syncthreads();
    ss = 0.f;
    #pragma unroll
    for (int i = 0; i < 8; ++i) ss += sh.red[i];
    const float inv = 1.0f / ss;

    // weighted value sum
    float4 o4 = make_float4(0.f, 0.f, 0.f, 0.f);
    #pragma unroll 8
    for (int k = 0; k < BLK_PER_TB; ++k) {
        const int slot = w + 8 * k;
        uint2 raw = reinterpret_cast<const uint2*>(Mv + (size_t)slot * DIM)[lane];
        float4 v = make_float4(0.f, 0.f, 0.f, 0.f);
        acc_u2(v, raw);
        const float p = sh.score[slot];
        o4.x += p * v.x; o4.y += p * v.y; o4.z += p * v.z; o4.w += p * v.w;
    }
    sh.part[w][lane] = o4;
    __syncthreads();

    if (w == 0) {
        float4 r = make_float4(0.f, 0.f, 0.f, 0.f);
        #pragma unroll
        for (int i = 0; i < 8; ++i) {
            float4 p = sh.part[i][lane];
            r.x += p.x; r.y += p.y; r.z += p.z; r.w += p.w;
        }
        float4 res;
        res.x = u4.x + r.x * inv;
        res.y = u4.y + r.y * inv;
        res.z = u4.z + r.z * inv;
        res.w = u4.w + r.w * inv;
        reinterpret_cast<float4*>(dst)[lane] = res;
    }
    __syncthreads();    // dst store complete before caller fences
}

__device__ void run_hop2(HopShared& sh, int b, float* __restrict__ out)
{
    const int w = threadIdx.x >> 5, lane = threadIdx.x & 31;
    if (w == 0)
        reinterpret_cast<float4*>(sh.u)[lane] =
            reinterpret_cast<const float4*>(g_u2 + b * DIM)[lane];
    __syncthreads();
    const __half* M2 = g_Mh + (size_t)(1 * BATCH + b) * SLOTS * DIM;
    const __half* M3 = g_Mh + (size_t)(2 * BATCH + b) * SLOTS * DIM;
    hop_block(sh, M2, M3, out + b * DIM);
}

// ---------------------------------------------------------------------------
// K2: gather tables 1,2,3 with fused per-batch hop continuations.
// ---------------------------------------------------------------------------
__global__ void __launch_bounds__(256) gather_kernel(
    const int* __restrict__ story, const int* __restrict__ kb,
    float* __restrict__ out)
{
    __shared__ HopShared sh;
    __shared__ int s_old;

    const int tid  = threadIdx.x;
    const int lane = tid & 31;
    const int w    = tid >> 5;
    const int tab  = blockIdx.x / GBLK_PER_TAB;        // 0,1,2 in launch order
    const int bit  = blockIdx.x % GBLK_PER_TAB;
    const int b    = bit / BLK_PER_TB;
    const int slot = (bit % BLK_PER_TB) * 8 + w;

    // ---- gather this warp's slot ----
    const __half* __restrict__ Ct = g_Ch + (size_t)tab * VOCAB * DIM;
    float4 acc = make_float4(0.f, 0.f, 0.f, 0.f);

    if (slot < M_SLOTS) {
        const int* toks = story + ((size_t)b * M_SLOTS + slot) * S_TOK;
        int tk[S_TOK];
        #pragma unroll
        for (int j = 0; j < S_TOK; ++j) tk[j] = toks[j];
        #pragma unroll
        for (int j = 0; j < S_TOK; ++j) {
            uint2 v = reinterpret_cast<const uint2*>(Ct + (size_t)tk[j] * DIM)[lane];
            acc_u2(acc, v);
        }
    } else {
        const int* toks = kb + ((size_t)b * T_TREE + (slot - M_SLOTS)) * L_TOK;
        float4 a0 = make_float4(0.f, 0.f, 0.f, 0.f);
        float4 a1 = a0, a2 = a0, a3 = a0;
        #pragma unroll 4
        for (int j = 0; j < L_TOK; j += 4) {
            int t0 = toks[j + 0], t1 = toks[j + 1];
            int t2 = toks[j + 2], t3 = toks[j + 3];
            uint2 v0 = reinterpret_cast<const uint2*>(Ct + (size_t)t0 * DIM)[lane];
            uint2 v1 = reinterpret_cast<const uint2*>(Ct + (size_t)t1 * DIM)[lane];
            uint2 v2 = reinterpret_cast<const uint2*>(Ct + (size_t)t2 * DIM)[lane];
            uint2 v3 = reinterpret_cast<const uint2*>(Ct + (size_t)t3 * DIM)[lane];
            acc_u2(a0, v0); acc_u2(a1, v1); acc_u2(a2, v2); acc_u2(a3, v3);
        }
        acc.x = (a0.x + a1.x) + (a2.x + a3.x);
        acc.y = (a0.y + a1.y) + (a2.y + a3.y);
        acc.z = (a0.z + a1.z) + (a2.z + a3.z);
        acc.w = (a0.w + a1.w) + (a2.w + a3.w);
    }

    union { __half2 h[2]; uint2 u; } st;
    st.h[0] = __floats2half2_rn(acc.x, acc.y);
    st.h[1] = __floats2half2_rn(acc.z, acc.w);
    reinterpret_cast<uint2*>(
        g_Mh + ((size_t)(tab * BATCH + b) * SLOTS + slot) * DIM)[lane] = st.u;

    // ---- continuation passing ----
    __threadfence();          // publish M writes
    __syncthreads();

    if (tab < 2) {
        if (tid == 0) s_old = atomicAdd(&g_cnt[b], 1);
        __syncthreads();
        if (s_old != 2 * BLK_PER_TB - 1) return;   // not last of M1+M2(b)
        if (tid == 0) g_cnt[b] = 0;                // reset for graph replay
        __threadfence();                           // acquire M1, M2

        // ---- u1(b) = mean over 640 slots of M1 ----
        const __half* M1 = g_Mh + (size_t)(0 * BATCH + b) * SLOTS * DIM;
        const __half* M2 = g_Mh + (size_t)(1 * BATCH + b) * SLOTS * DIM;
        float4 a = make_float4(0.f, 0.f, 0.f, 0.f);
        #pragma unroll 8
        for (int k = 0; k < BLK_PER_TB; ++k) {
            uint2 raw = reinterpret_cast<const uint2*>(
                M1 + (size_t)(w + 8 * k) * DIM)[lane];
            acc_u2(a, raw);
        }
        sh.part[w][lane] = a;
        __syncthreads();
        if (w == 0) {
            float4 r = make_float4(0.f, 0.f, 0.f, 0.f);
            #pragma unroll
            for (int i = 0; i < 8; ++i) {
                float4 p = sh.part[i][lane];
                r.x += p.x; r.y += p.y; r.z += p.z; r.w += p.w;
            }
            const float sc = 1.0f / SLOTS;
            r.x *= sc; r.y *= sc; r.z *= sc; r.w *= sc;
            reinterpret_cast<float4*>(sh.u)[lane] = r;
        }
        __syncthreads();

        // ---- hop 1: keys M1, values M2 -> u2[b] ----
        hop_block(sh, M1, M2, g_u2 + b * DIM);
        __threadfence();                           // publish u2[b]
        if (tid == 0) s_old = atomicAdd(&g_cnt[BATCH + b], 1);
        __syncthreads();
        if (s_old == BLK_PER_TB) {                 // M3(b) already done too
            if (tid == 0) g_cnt[BATCH + b] = 0;
            __threadfence();
            run_hop2(sh, b, out);
        }
    } else {
        if (tid == 0) s_old = atomicAdd(&g_cnt[BATCH + b], 1);
        __syncthreads();
        if (s_old == BLK_PER_TB) {                 // last of M3(b) + hop1(b)
            if (tid == 0) g_cnt[BATCH + b] = 0;
            __threadfence();                       // acquire M3, u2
            run_hop2(sh, b, out);
        }
    }
}

// ---------------------------------------------------------------------------
extern "C" void kernel_launch(void* const* d_in, const int* in_sizes, int n_in,
                              void* d_out, int out_size)
{
    const float* C     = (const float*)d_in[0];  // [4, 50257, 128]
    const int*   story = (const int*)  d_in[1];  // [32, 512, 6]
    const int*   kb    = (const int*)  d_in[2];  // [32, 128, 64]
    float*       out   = (float*)d_out;          // [32, 128]

    const int cthreads = (int)(CN / 8);                      // 2,412,336
    convert_kernel<<<(cthreads + 255) / 256, 256>>>(C);      // fp32 -> fp16
    gather_kernel<<<3 * GBLK_PER_TAB, 256>>>(story, kb, out); // gather + hops
}

// round 10
// speedup vs baseline: 1.6639x; 1.6639x over previous
#include <cuda_runtime.h>
#include <cuda_fp16.h>

#define VOCAB   50257
#define DIM     128
#define BATCH   32
#define M_SLOTS 512
#define S_TOK   6
#define T_TREE  128
#define L_TOK   64
#define SLOTS   (M_SLOTS + T_TREE)       // 640
#define CN      ((size_t)3 * VOCAB * DIM)

#define HW_BLK   16                       // halfwarps (slots) per gather block
#define GGRID    (3 * BATCH * SLOTS / HW_BLK)   // 3840 gather blocks
#define HOP_T    512                      // threads per hop block
#define HW_HOP   (HOP_T / 16)             // 32 halfwarps per hop block
#define SL_HW    (SLOTS / HW_HOP)         // 20 slots per halfwarp

// fp16 tables 1..3 (38.6 MB) and fp16 slot memories (15.7 MB)
__device__ __align__(16) __half g_Ch[CN];
__device__ __align__(16) __half g_Mh[(size_t)3 * BATCH * SLOTS * DIM];

__device__ __forceinline__ float warp_max(float v) {
    #pragma unroll
    for (int o = 16; o; o >>= 1) v = fmaxf(v, __shfl_xor_sync(0xffffffffu, v, o));
    return v;
}
__device__ __forceinline__ float warp_sum(float v) {
    #pragma unroll
    for (int o = 16; o; o >>= 1) v += __shfl_xor_sync(0xffffffffu, v, o);
    return v;
}
// accumulate 8 fp16 values (uint4) into two float4s
__device__ __forceinline__ void acc8(float4& lo, float4& hi, uint4 v) {
    float2 f;
    f = __half22float2(*reinterpret_cast<__half2*>(&v.x)); lo.x += f.x; lo.y += f.y;
    f = __half22float2(*reinterpret_cast<__half2*>(&v.y)); lo.z += f.x; lo.w += f.y;
    f = __half22float2(*reinterpret_cast<__half2*>(&v.z)); hi.x += f.x; hi.y += f.y;
    f = __half22float2(*reinterpret_cast<__half2*>(&v.w)); hi.z += f.x; hi.w += f.y;
}
__device__ __forceinline__ uint4 pack8(float4 lo, float4 hi) {
    union { __half2 h[4]; uint4 u; } cv;
    cv.h[0] = __floats2half2_rn(lo.x, lo.y);
    cv.h[1] = __floats2half2_rn(lo.z, lo.w);
    cv.h[2] = __floats2half2_rn(hi.x, hi.y);
    cv.h[3] = __floats2half2_rn(hi.z, hi.w);
    return cv.u;
}
// dot of 8 fp16 values with 8 floats
__device__ __forceinline__ float dot8(uint4 v, const float* __restrict__ u) {
    float2 f; float s;
    f = __half22float2(*reinterpret_cast<__half2*>(&v.x)); s  = f.x * u[0] + f.y * u[1];
    f = __half22float2(*reinterpret_cast<__half2*>(&v.y)); s += f.x * u[2] + f.y * u[3];
    f = __half22float2(*reinterpret_cast<__half2*>(&v.z)); s += f.x * u[4] + f.y * u[5];
    f = __half22float2(*reinterpret_cast<__half2*>(&v.w)); s += f.x * u[6] + f.y * u[7];
    return s;
}
// reduce within a 16-lane halfwarp
__device__ __forceinline__ float hw_sum(float v) {
    #pragma unroll
    for (int o = 8; o; o >>= 1) v += __shfl_xor_sync(0xffffffffu, v, o);
    return v;
}

// ---------------------------------------------------------------------------
// K1: convert C tables 1..3 to fp16 (streaming reads).
// ---------------------------------------------------------------------------
__global__ void __launch_bounds__(256) convert_kernel(const float* __restrict__ C)
{
    const size_t i = ((size_t)blockIdx.x * 256 + threadIdx.x) * 8;
    if (i >= CN) return;
    const float4* src = reinterpret_cast<const float4*>(C + (size_t)VOCAB * DIM + i);
    float4 a = __ldcs(src);
    float4 b = __ldcs(src + 1);
    union { __half2 h[4]; uint4 u; } cv;
    cv.h[0] = __floats2half2_rn(a.x, a.y);
    cv.h[1] = __floats2half2_rn(a.z, a.w);
    cv.h[2] = __floats2half2_rn(b.x, b.y);
    cv.h[3] = __floats2half2_rn(b.z, b.w);
    *reinterpret_cast<uint4*>(g_Ch + i) = cv.u;
}

// ---------------------------------------------------------------------------
// K2: gather-sum tables 1..3. HALF-WARP per slot: 16 lanes x uint4 = one
// 256-B fp16 row per load instruction. No fences, no atomics.
// ---------------------------------------------------------------------------
__global__ void __launch_bounds__(256) gather_kernel(
    const int* __restrict__ story, const int* __restrict__ kb)
{
    const int hw   = threadIdx.x >> 4;               // halfwarp in block 0..15
    const int hl   = threadIdx.x & 15;               // lane in halfwarp
    const int gid  = blockIdx.x * HW_BLK + hw;       // global slot index
    const int tab  = gid / (BATCH * SLOTS);          // 0..2 -> table tab+1
    const int rem  = gid % (BATCH * SLOTS);
    const int b    = rem / SLOTS;
    const int slot = rem % SLOTS;

    const __half* __restrict__ Ct = g_Ch + (size_t)tab * VOCAB * DIM;

    float4 lo = make_float4(0.f, 0.f, 0.f, 0.f);
    float4 hi = lo;

    if (slot < M_SLOTS) {
        const int* toks = story + ((size_t)b * M_SLOTS + slot) * S_TOK;
        int tk[S_TOK];
        #pragma unroll
        for (int j = 0; j < S_TOK; ++j) tk[j] = toks[j];
        #pragma unroll
        for (int j = 0; j < S_TOK; ++j) {
            uint4 v = reinterpret_cast<const uint4*>(Ct + (size_t)tk[j] * DIM)[hl];
            acc8(lo, hi, v);
        }
    } else {
        const int* toks = kb + ((size_t)b * T_TREE + (slot - M_SLOTS)) * L_TOK;
        float4 lo1 = lo, hi1 = hi;
        #pragma unroll 8
        for (int j = 0; j < L_TOK; j += 2) {
            int t0 = toks[j], t1 = toks[j + 1];
            uint4 v0 = reinterpret_cast<const uint4*>(Ct + (size_t)t0 * DIM)[hl];
            uint4 v1 = reinterpret_cast<const uint4*>(Ct + (size_t)t1 * DIM)[hl];
            acc8(lo, hi, v0);
            acc8(lo1, hi1, v1);
        }
        lo.x += lo1.x; lo.y += lo1.y; lo.z += lo1.z; lo.w += lo1.w;
        hi.x += hi1.x; hi.y += hi1.y; hi.z += hi1.z; hi.w += hi1.w;
    }

    reinterpret_cast<uint4*>(g_Mh + (size_t)gid * DIM)[hl] = pack8(lo, hi);
}

// ---------------------------------------------------------------------------
// K3: the entire 3-hop chain, one block per batch element.
//   u1 = mean(M1); hop1: softmax(M1 u1) @ M2; hop2: softmax(M2 u2) @ M3.
// All state in shared; 512 threads = 32 halfwarps x 20 slots each.
// ---------------------------------------------------------------------------
__global__ void __launch_bounds__(HOP_T) hops_kernel(float* __restrict__ out)
{
    __shared__ float s_score[SLOTS];
    __shared__ float s_part[HW_HOP][DIM];   // 16 KB
    __shared__ float s_u[DIM];
    __shared__ float s_red[16];

    const int b    = blockIdx.x;
    const int tid  = threadIdx.x;
    const int w    = tid >> 5;
    const int lane = tid & 31;
    const int hw   = tid >> 4;      // 0..31
    const int hl   = tid & 15;

    const __half* __restrict__ M1 = g_Mh + (size_t)(0 * BATCH + b) * SLOTS * DIM;
    const __half* __restrict__ M2 = g_Mh + (size_t)(1 * BATCH + b) * SLOTS * DIM;
    const __half* __restrict__ M3 = g_Mh + (size_t)(2 * BATCH + b) * SLOTS * DIM;

    // ---------- u1 = mean over slots of M1 ----------
    {
        float4 lo = make_float4(0.f, 0.f, 0.f, 0.f), hi = lo;
        #pragma unroll 5
        for (int k = 0; k < SL_HW; ++k) {
            uint4 v = reinterpret_cast<const uint4*>(
                M1 + (size_t)(hw * SL_HW + k) * DIM)[hl];
            acc8(lo, hi, v);
        }
        float* p = &s_part[hw][hl * 8];
        p[0] = lo.x; p[1] = lo.y; p[2] = lo.z; p[3] = lo.w;
        p[4] = hi.x; p[5] = hi.y; p[6] = hi.z; p[7] = hi.w;
    }
    __syncthreads();
    if (tid < DIM) {
        float s = 0.f;
        #pragma unroll
        for (int i = 0; i < HW_HOP; ++i) s += s_part[i][tid];
        s_u[tid] = s * (1.0f / SLOTS);
    }
    __syncthreads();

    // ---------- two hops ----------
    #pragma unroll
    for (int hop = 0; hop < 2; ++hop) {
        const __half* Mk = (hop == 0) ? M1 : M2;
        const __half* Mv = (hop == 0) ? M2 : M3;

        // u into registers (8 dims per lane)
        float ur[8];
        #pragma unroll
        for (int j = 0; j < 8; ++j) ur[j] = s_u[hl * 8 + j];

        // scores
        #pragma unroll 5
        for (int k = 0; k < SL_HW; ++k) {
            const int slot = hw * SL_HW + k;
            uint4 v = reinterpret_cast<const uint4*>(Mk + (size_t)slot * DIM)[hl];
            float p = hw_sum(dot8(v, ur));
            if (hl == 0) s_score[slot] = p;
        }
        __syncthreads();

        // softmax over 640
        float mx = -1e30f;
        for (int i = tid; i < SLOTS; i += HOP_T) mx = fmaxf(mx, s_score[i]);
        mx = warp_max(mx);
        if (lane == 0) s_red[w] = mx;
        __syncthreads();
        mx = s_red[0];
        #pragma unroll
        for (int i = 1; i < 16; ++i) mx = fmaxf(mx, s_red[i]);

        float ss = 0.f;
        for (int i = tid; i < SLOTS; i += HOP_T) {
            float e = __expf(s_score[i] - mx);
            s_score[i] = e;
            ss += e;
        }
        ss = warp_sum(ss);
        __syncthreads();                 // maxes consumed; e-writes pending
        if (lane == 0) s_red[w] = ss;
        __syncthreads();
        ss = 0.f;
        #pragma unroll
        for (int i = 0; i < 16; ++i) ss += s_red[i];
        const float inv = 1.0f / ss;

        // weighted value sum
        {
            float4 lo = make_float4(0.f, 0.f, 0.f, 0.f), hi = lo;
            #pragma unroll 5
            for (int k = 0; k < SL_HW; ++k) {
                const int slot = hw * SL_HW + k;
                const float p = s_score[slot];
                uint4 v = reinterpret_cast<const uint4*>(Mv + (size_t)slot * DIM)[hl];
                float2 f;
                f = __half22float2(*reinterpret_cast<__half2*>(&v.x)); lo.x += p * f.x; lo.y += p * f.y;
                f = __half22float2(*reinterpret_cast<__half2*>(&v.y)); lo.z += p * f.x; lo.w += p * f.y;
                f = __half22float2(*reinterpret_cast<__half2*>(&v.z)); hi.x += p * f.x; hi.y += p * f.y;
                f = __half22float2(*reinterpret_cast<__half2*>(&v.w)); hi.z += p * f.x; hi.w += p * f.y;
            }
            float* p = &s_part[hw][hl * 8];
            p[0] = lo.x; p[1] = lo.y; p[2] = lo.z; p[3] = lo.w;
            p[4] = hi.x; p[5] = hi.y; p[6] = hi.z; p[7] = hi.w;
        }
        __syncthreads();

        if (tid < DIM) {
            float o = 0.f;
            #pragma unroll
            for (int i = 0; i < HW_HOP; ++i) o += s_part[i][tid];
            const float un = s_u[tid] + o * inv;
            if (hop == 0) s_u[tid] = un;
            else          out[b * DIM + tid] = un;
        }
        __syncthreads();
    }
}

// ---------------------------------------------------------------------------
extern "C" void kernel_launch(void* const* d_in, const int* in_sizes, int n_in,
                              void* d_out, int out_size)
{
    const float* C     = (const float*)d_in[0];  // [4, 50257, 128]
    const int*   story = (const int*)  d_in[1];  // [32, 512, 6]
    const int*   kb    = (const int*)  d_in[2];  // [32, 128, 64]
    float*       out   = (float*)d_out;          // [32, 128]

    const int cthreads = (int)(CN / 8);                      // 2,412,336
    convert_kernel<<<(cthreads + 255) / 256, 256>>>(C);      // fp32 -> fp16
    gather_kernel<<<GGRID, 256>>>(story, kb);                // 3840 blocks
    hops_kernel<<<BATCH, HOP_T>>>(out);                      // whole 3-hop chain
}